// round 6
// baseline (speedup 1.0000x reference)
#include <cuda_runtime.h>

// ============================================================
// Compile-time Clebsch-Gordan (Racah formula, evaluated by the
// C++ frontend; every coefficient is an FFMA immediate in SASS).
// ============================================================
__host__ __device__ constexpr double cfact(int n) {
    double r = 1.0;
    for (int i = 2; i <= n; ++i) r *= (double)i;
    return r;
}
__host__ __device__ constexpr double csqrt_(double x) {
    double g = x > 1.0 ? x : 1.0;
    for (int i = 0; i < 100; ++i) g = 0.5 * (g + x / g);
    return g;
}
__host__ __device__ constexpr double cgc(int j1, int m1, int j2, int m2, int j, int m) {
    double pre = csqrt_((2.0 * j + 1.0) * cfact(j + j1 - j2) * cfact(j - j1 + j2) *
                        cfact(j1 + j2 - j) / cfact(j1 + j2 + j + 1));
    pre = pre * csqrt_(cfact(j + m) * cfact(j - m) * cfact(j1 - m1) * cfact(j1 + m1) *
                       cfact(j2 - m2) * cfact(j2 + m2));
    int vmin = 0;
    if (j2 - j - m1 > vmin) vmin = j2 - j - m1;
    if (j1 + m2 - j > vmin) vmin = j1 + m2 - j;
    int vmax = j1 + j2 - j;
    if (j1 - m1 < vmax) vmax = j1 - m1;
    if (j2 + m2 < vmax) vmax = j2 + m2;
    double s = 0.0;
    for (int v = vmin; v <= vmax; ++v) {
        double t = 1.0 / (cfact(v) * cfact(j1 + j2 - j - v) * cfact(j1 - m1 - v) *
                          cfact(j2 + m2 - v) * cfact(j - j2 + m1 + v) * cfact(j - j1 - m2 + v));
        s += (v % 2 == 0) ? t : -t;
    }
    return pre * s;
}

__device__ __forceinline__ float4 cmul(const float4 a, const float4 b) {
    return make_float4(a.x * b.x - a.y * b.y, a.x * b.y + a.y * b.x,
                       a.z * b.z - a.w * b.w, a.z * b.w + a.w * b.z);
}
__device__ __forceinline__ float4 neg4(const float4 v) {
    return make_float4(-v.x, -v.y, -v.z, -v.w);
}

// ---- CG row: recompute complex products on the fly (short live ranges).
template <int L1, int L2, int L, int MI, int M1I>
__device__ __forceinline__ void cg_acc(float4& acc, const float4 (&A)[2 * L1 + 1],
                                       const float4 (&B)[2 * L2 + 1]) {
    constexpr int m  = MI - L;
    constexpr int m1 = M1I - L1;
    constexpr int m2 = m - m1;
    if constexpr (m2 >= -L2 && m2 <= L2) {
        constexpr float c = (float)cgc(L1, m1, L2, m2, L, m);
        if constexpr (c != 0.0f) {
            const float4 q = cmul(A[M1I], B[m2 + L2]);
            acc.x = fmaf(c, q.x, acc.x);
            acc.y = fmaf(c, q.y, acc.y);
            acc.z = fmaf(c, q.z, acc.z);
            acc.w = fmaf(c, q.w, acc.w);
        }
    }
    if constexpr (M1I + 1 <= 2 * L1) cg_acc<L1, L2, L, MI, M1I + 1>(acc, A, B);
}

template <int L1, int L2, int L, int MI>
__device__ __forceinline__ float4 cg_row(const float4 (&A)[2 * L1 + 1],
                                         const float4 (&B)[2 * L2 + 1]) {
    float4 acc = make_float4(0.f, 0.f, 0.f, 0.f);
    cg_acc<L1, L2, L, MI, 0>(acc, A, B);
    return acc;
}

template <int L1, int L2, int L, int MI = 0, class F>
__device__ __forceinline__ void cg_rows(const float4 (&A)[2 * L1 + 1],
                                        const float4 (&B)[2 * L2 + 1], F&& f) {
    f(MI, cg_row<L1, L2, L, MI>(A, B));
    if constexpr (MI + 1 <= 2 * L) cg_rows<L1, L2, L, MI + 1>(A, B, f);
}

// ============================================================
// Output layout (float4 units). Parts l=0..4 concatenated:
// shapes (1024, 2l+1, n_l*512, 2), n = {3, 6, 6, 3, 1}.
// ============================================================
static constexpr int P1 = 786432;
static constexpr int P2 = 5505024;
static constexpr int P3 = 13369344;
static constexpr int P4 = 18874368;

// Work split across blockIdx.y:
//   y=0 -> parts l=0 (3), l=1 (18), l=3 (21)  = 42 float4/thread
//   y=1 -> parts l=2 (30), l=4 (9)            = 39 float4/thread
// Inputs are L2-resident (37.7 MB), so the double-read is free at DRAM.
__global__ void __launch_bounds__(256, 2) cg_kernel(
    const float4* __restrict__ x0, const float4* __restrict__ x1,
    const float4* __restrict__ x2, float4* __restrict__ out) {
    const int c4 = threadIdx.x;  // channel-pair index 0..255
    const int b  = blockIdx.x;   // batch 0..1023

    float4 a0[1], a1[3], a2[5];
    a0[0] = x0[b * 256 + c4];
#pragma unroll
    for (int i = 0; i < 3; ++i) a1[i] = x1[(b * 3 + i) * 256 + c4];
#pragma unroll
    for (int i = 0; i < 5; ++i) a2[i] = x2[(b * 5 + i) * 256 + c4];

    const float4 zf = make_float4(0.f, 0.f, 0.f, 0.f);

    if (blockIdx.y == 0) {
        // ---- l=0 part: k0=(0,0,0), k1=(1,1,0), k2=(2,2,0)
        out[b * 768 + c4]           = cmul(a0[0], a0[0]);
        out[b * 768 + 256 + c4]     = cg_row<1, 1, 0, 0>(a1, a1);
        out[b * 768 + 2 * 256 + c4] = cg_row<2, 2, 0, 0>(a2, a2);

        // ---- l=1 part (6 k): k0=(0,1), k1=(1,0) identical (C=1);
        //      k2=(1,1,1)=0, k5=(2,2,1)=0 (antisymmetric self-products).
#pragma unroll
        for (int m = 0; m < 3; ++m) {
            const float4 p = cmul(a0[0], a1[m]);
            const int base = P1 + (b * 3 + m) * 1536 + c4;
            out[base]           = p;
            out[base + 256]     = p;
            out[base + 2 * 256] = zf;
            out[base + 5 * 256] = zf;
        }
        // k3=(1,2,1), k4=(2,1,1) (sign +1)
        cg_rows<1, 2, 1>(a1, a2, [&](int mi, float4 v) {
            const int base = P1 + (b * 3 + mi) * 1536 + c4;
            out[base + 3 * 256] = v;
            out[base + 4 * 256] = v;
        });

        // ---- l=3 part (3 k): k0=(1,2,3), k1=(2,1,3) (+1), k2=(2,2,3)=0
        cg_rows<1, 2, 3>(a1, a2, [&](int mi, float4 v) {
            const int base = P3 + (b * 7 + mi) * 768 + c4;
            out[base]           = v;
            out[base + 256]     = v;
            out[base + 2 * 256] = zf;
        });
    } else {
        // ---- l=2 part (6 k): k0=(0,2), k3=(2,0) identical (C=1)
#pragma unroll
        for (int m = 0; m < 5; ++m) {
            const float4 p = cmul(a0[0], a2[m]);
            const int base = P2 + (b * 5 + m) * 1536 + c4;
            out[base]           = p;
            out[base + 3 * 256] = p;
        }
        // k1=(1,1,2)
        cg_rows<1, 1, 2>(a1, a1, [&](int mi, float4 v) {
            out[P2 + (b * 5 + mi) * 1536 + 256 + c4] = v;
        });
        // k2=(1,2,2), k4=(2,1,2) = -(1,2,2)
        cg_rows<1, 2, 2>(a1, a2, [&](int mi, float4 v) {
            const int base = P2 + (b * 5 + mi) * 1536 + c4;
            out[base + 2 * 256] = v;
            out[base + 4 * 256] = neg4(v);
        });
        // k5=(2,2,2)
        cg_rows<2, 2, 2>(a2, a2, [&](int mi, float4 v) {
            out[P2 + (b * 5 + mi) * 1536 + 5 * 256 + c4] = v;
        });

        // ---- l=4 part (1 k): (2,2,4)
        cg_rows<2, 2, 4>(a2, a2, [&](int mi, float4 v) {
            out[P4 + (b * 9 + mi) * 256 + c4] = v;
        });
    }
}

extern "C" void kernel_launch(void* const* d_in, const int* in_sizes, int n_in,
                              void* d_out, int out_size) {
    const float4* x0 = nullptr;
    const float4* x1 = nullptr;
    const float4* x2 = nullptr;
    for (int i = 0; i < n_in; ++i) {
        if (in_sizes[i] == 1024 * 1 * 512 * 2)      x0 = (const float4*)d_in[i];
        else if (in_sizes[i] == 1024 * 3 * 512 * 2) x1 = (const float4*)d_in[i];
        else if (in_sizes[i] == 1024 * 5 * 512 * 2) x2 = (const float4*)d_in[i];
    }
    dim3 grid(1024, 2);
    cg_kernel<<<grid, 256>>>(x0, x1, x2, (float4*)d_out);
}

// round 14
// speedup vs baseline: 1.1486x; 1.1486x over previous
#include <cuda_runtime.h>

// ============================================================
// Compile-time Clebsch-Gordan (Racah formula, evaluated by the
// C++ frontend; every coefficient is an FFMA immediate in SASS).
// ============================================================
__host__ __device__ constexpr double cfact(int n) {
    double r = 1.0;
    for (int i = 2; i <= n; ++i) r *= (double)i;
    return r;
}
__host__ __device__ constexpr double csqrt_(double x) {
    double g = x > 1.0 ? x : 1.0;
    for (int i = 0; i < 100; ++i) g = 0.5 * (g + x / g);
    return g;
}
__host__ __device__ constexpr double cgc(int j1, int m1, int j2, int m2, int j, int m) {
    double pre = csqrt_((2.0 * j + 1.0) * cfact(j + j1 - j2) * cfact(j - j1 + j2) *
                        cfact(j1 + j2 - j) / cfact(j1 + j2 + j + 1));
    pre = pre * csqrt_(cfact(j + m) * cfact(j - m) * cfact(j1 - m1) * cfact(j1 + m1) *
                       cfact(j2 - m2) * cfact(j2 + m2));
    int vmin = 0;
    if (j2 - j - m1 > vmin) vmin = j2 - j - m1;
    if (j1 + m2 - j > vmin) vmin = j1 + m2 - j;
    int vmax = j1 + j2 - j;
    if (j1 - m1 < vmax) vmax = j1 - m1;
    if (j2 + m2 < vmax) vmax = j2 + m2;
    double s = 0.0;
    for (int v = vmin; v <= vmax; ++v) {
        double t = 1.0 / (cfact(v) * cfact(j1 + j2 - j - v) * cfact(j1 - m1 - v) *
                          cfact(j2 + m2 - v) * cfact(j - j2 + m1 + v) * cfact(j - j1 - m2 + v));
        s += (v % 2 == 0) ? t : -t;
    }
    return pre * s;
}

__device__ __forceinline__ float2 cmul(const float2 a, const float2 b) {
    return make_float2(a.x * b.x - a.y * b.y, a.x * b.y + a.y * b.x);
}
__device__ __forceinline__ float2 neg2(const float2 v) {
    return make_float2(-v.x, -v.y);
}

// ---- CG row: recompute complex products on the fly (short live ranges).
template <int L1, int L2, int L, int MI, int M1I>
__device__ __forceinline__ void cg_acc(float2& acc, const float2 (&A)[2 * L1 + 1],
                                       const float2 (&B)[2 * L2 + 1]) {
    constexpr int m  = MI - L;
    constexpr int m1 = M1I - L1;
    constexpr int m2 = m - m1;
    if constexpr (m2 >= -L2 && m2 <= L2) {
        constexpr float c = (float)cgc(L1, m1, L2, m2, L, m);
        if constexpr (c != 0.0f) {
            const float2 q = cmul(A[M1I], B[m2 + L2]);
            acc.x = fmaf(c, q.x, acc.x);
            acc.y = fmaf(c, q.y, acc.y);
        }
    }
    if constexpr (M1I + 1 <= 2 * L1) cg_acc<L1, L2, L, MI, M1I + 1>(acc, A, B);
}

template <int L1, int L2, int L, int MI>
__device__ __forceinline__ float2 cg_row(const float2 (&A)[2 * L1 + 1],
                                         const float2 (&B)[2 * L2 + 1]) {
    float2 acc = make_float2(0.f, 0.f);
    cg_acc<L1, L2, L, MI, 0>(acc, A, B);
    return acc;
}

template <int L1, int L2, int L, int MI = 0, class F>
__device__ __forceinline__ void cg_rows(const float2 (&A)[2 * L1 + 1],
                                        const float2 (&B)[2 * L2 + 1], F&& f) {
    f(MI, cg_row<L1, L2, L, MI>(A, B));
    if constexpr (MI + 1 <= 2 * L) cg_rows<L1, L2, L, MI + 1>(A, B, f);
}

// ============================================================
// Output layout (float2 = one complex). Parts l=0..4 concat:
// shapes (1024, 2l+1, n_l*512, 2), n = {3, 6, 6, 3, 1}.
// Row length per (b, m, k) = 512 complex.
// ============================================================
static constexpr int Q1 = 1572864;   // P1*2
static constexpr int Q2 = 11010048;  // P2*2
static constexpr int Q3 = 26738688;  // P3*2
static constexpr int Q4 = 37748736;  // P4*2

// One complex channel per thread. blockIdx.y picks the channel half
// (c = tid + 256*y) -> NO duplicated DRAM traffic (disjoint channels),
// half the register pressure of the float4 version -> 3 CTAs/SM.
__global__ void __launch_bounds__(256, 3) cg_kernel(
    const float2* __restrict__ x0, const float2* __restrict__ x1,
    const float2* __restrict__ x2, float2* __restrict__ out) {
    const int c = threadIdx.x + (blockIdx.y << 8);  // channel 0..511
    const int b = blockIdx.x;                       // batch 0..1023

    float2 a0[1], a1[3], a2[5];
    a0[0] = x0[b * 512 + c];
#pragma unroll
    for (int i = 0; i < 3; ++i) a1[i] = x1[(b * 3 + i) * 512 + c];
#pragma unroll
    for (int i = 0; i < 5; ++i) a2[i] = x2[(b * 5 + i) * 512 + c];

    const float2 zf = make_float2(0.f, 0.f);

    // ---- l=0 part: k0=(0,0,0), k1=(1,1,0), k2=(2,2,0)
    {
        const int base = b * 1536 + c;
        __stcs(&out[base],            cmul(a0[0], a0[0]));
        __stcs(&out[base + 512],      cg_row<1, 1, 0, 0>(a1, a1));
        __stcs(&out[base + 2 * 512],  cg_row<2, 2, 0, 0>(a2, a2));
    }

    // ---- l=1 part (6 k): k0=(0,1), k1=(1,0) identical (C=1);
    //      k2=(1,1,1)=0, k5=(2,2,1)=0 (antisymmetric self-products).
#pragma unroll
    for (int m = 0; m < 3; ++m) {
        const float2 p = cmul(a0[0], a1[m]);
        const int base = Q1 + (b * 3 + m) * 3072 + c;
        __stcs(&out[base],           p);
        __stcs(&out[base + 512],     p);
        __stcs(&out[base + 2 * 512], zf);
        __stcs(&out[base + 5 * 512], zf);
    }
    // k3=(1,2,1), k4=(2,1,1) (sign +1)
    cg_rows<1, 2, 1>(a1, a2, [&](int mi, float2 v) {
        const int base = Q1 + (b * 3 + mi) * 3072 + c;
        __stcs(&out[base + 3 * 512], v);
        __stcs(&out[base + 4 * 512], v);
    });

    // ---- l=2 part (6 k): k0=(0,2), k3=(2,0) identical (C=1)
#pragma unroll
    for (int m = 0; m < 5; ++m) {
        const float2 p = cmul(a0[0], a2[m]);
        const int base = Q2 + (b * 5 + m) * 3072 + c;
        __stcs(&out[base],           p);
        __stcs(&out[base + 3 * 512], p);
    }
    // k1=(1,1,2)
    cg_rows<1, 1, 2>(a1, a1, [&](int mi, float2 v) {
        __stcs(&out[Q2 + (b * 5 + mi) * 3072 + 512 + c], v);
    });
    // k2=(1,2,2), k4=(2,1,2) = -(1,2,2)
    cg_rows<1, 2, 2>(a1, a2, [&](int mi, float2 v) {
        const int base = Q2 + (b * 5 + mi) * 3072 + c;
        __stcs(&out[base + 2 * 512], v);
        __stcs(&out[base + 4 * 512], neg2(v));
    });
    // k5=(2,2,2)
    cg_rows<2, 2, 2>(a2, a2, [&](int mi, float2 v) {
        __stcs(&out[Q2 + (b * 5 + mi) * 3072 + 5 * 512 + c], v);
    });

    // ---- l=3 part (3 k): k0=(1,2,3), k1=(2,1,3) (+1), k2=(2,2,3)=0
    cg_rows<1, 2, 3>(a1, a2, [&](int mi, float2 v) {
        const int base = Q3 + (b * 7 + mi) * 1536 + c;
        __stcs(&out[base],           v);
        __stcs(&out[base + 512],     v);
        __stcs(&out[base + 2 * 512], zf);
    });

    // ---- l=4 part (1 k): (2,2,4)
    cg_rows<2, 2, 4>(a2, a2, [&](int mi, float2 v) {
        __stcs(&out[Q4 + (b * 9 + mi) * 512 + c], v);
    });
}

extern "C" void kernel_launch(void* const* d_in, const int* in_sizes, int n_in,
                              void* d_out, int out_size) {
    const float2* x0 = nullptr;
    const float2* x1 = nullptr;
    const float2* x2 = nullptr;
    for (int i = 0; i < n_in; ++i) {
        if (in_sizes[i] == 1024 * 1 * 512 * 2)      x0 = (const float2*)d_in[i];
        else if (in_sizes[i] == 1024 * 3 * 512 * 2) x1 = (const float2*)d_in[i];
        else if (in_sizes[i] == 1024 * 5 * 512 * 2) x2 = (const float2*)d_in[i];
    }
    dim3 grid(1024, 2);
    cg_kernel<<<grid, 256>>>(x0, x1, x2, (float2*)d_out);
}

// round 17
// speedup vs baseline: 1.1593x; 1.0094x over previous
#include <cuda_runtime.h>

// ============================================================
// Compile-time Clebsch-Gordan (Racah formula, evaluated by the
// C++ frontend; every coefficient is an FFMA immediate in SASS).
// ============================================================
__host__ __device__ constexpr double cfact(int n) {
    double r = 1.0;
    for (int i = 2; i <= n; ++i) r *= (double)i;
    return r;
}
__host__ __device__ constexpr double csqrt_(double x) {
    double g = x > 1.0 ? x : 1.0;
    for (int i = 0; i < 100; ++i) g = 0.5 * (g + x / g);
    return g;
}
__host__ __device__ constexpr double cgc(int j1, int m1, int j2, int m2, int j, int m) {
    double pre = csqrt_((2.0 * j + 1.0) * cfact(j + j1 - j2) * cfact(j - j1 + j2) *
                        cfact(j1 + j2 - j) / cfact(j1 + j2 + j + 1));
    pre = pre * csqrt_(cfact(j + m) * cfact(j - m) * cfact(j1 - m1) * cfact(j1 + m1) *
                       cfact(j2 - m2) * cfact(j2 + m2));
    int vmin = 0;
    if (j2 - j - m1 > vmin) vmin = j2 - j - m1;
    if (j1 + m2 - j > vmin) vmin = j1 + m2 - j;
    int vmax = j1 + j2 - j;
    if (j1 - m1 < vmax) vmax = j1 - m1;
    if (j2 + m2 < vmax) vmax = j2 + m2;
    double s = 0.0;
    for (int v = vmin; v <= vmax; ++v) {
        double t = 1.0 / (cfact(v) * cfact(j1 + j2 - j - v) * cfact(j1 - m1 - v) *
                          cfact(j2 + m2 - v) * cfact(j - j2 + m1 + v) * cfact(j - j1 - m2 + v));
        s += (v % 2 == 0) ? t : -t;
    }
    return pre * s;
}

__device__ __forceinline__ float4 cmul(const float4 a, const float4 b) {
    return make_float4(a.x * b.x - a.y * b.y, a.x * b.y + a.y * b.x,
                       a.z * b.z - a.w * b.w, a.z * b.w + a.w * b.z);
}
__device__ __forceinline__ float4 neg4(const float4 v) {
    return make_float4(-v.x, -v.y, -v.z, -v.w);
}

// ---- CG row: recompute complex products on the fly (short live ranges).
template <int L1, int L2, int L, int MI, int M1I>
__device__ __forceinline__ void cg_acc(float4& acc, const float4 (&A)[2 * L1 + 1],
                                       const float4 (&B)[2 * L2 + 1]) {
    constexpr int m  = MI - L;
    constexpr int m1 = M1I - L1;
    constexpr int m2 = m - m1;
    if constexpr (m2 >= -L2 && m2 <= L2) {
        constexpr float c = (float)cgc(L1, m1, L2, m2, L, m);
        if constexpr (c != 0.0f) {
            const float4 q = cmul(A[M1I], B[m2 + L2]);
            acc.x = fmaf(c, q.x, acc.x);
            acc.y = fmaf(c, q.y, acc.y);
            acc.z = fmaf(c, q.z, acc.z);
            acc.w = fmaf(c, q.w, acc.w);
        }
    }
    if constexpr (M1I + 1 <= 2 * L1) cg_acc<L1, L2, L, MI, M1I + 1>(acc, A, B);
}

template <int L1, int L2, int L, int MI>
__device__ __forceinline__ float4 cg_row(const float4 (&A)[2 * L1 + 1],
                                         const float4 (&B)[2 * L2 + 1]) {
    float4 acc = make_float4(0.f, 0.f, 0.f, 0.f);
    cg_acc<L1, L2, L, MI, 0>(acc, A, B);
    return acc;
}

template <int L1, int L2, int L, int MI = 0, class F>
__device__ __forceinline__ void cg_rows(const float4 (&A)[2 * L1 + 1],
                                        const float4 (&B)[2 * L2 + 1], F&& f) {
    f(MI, cg_row<L1, L2, L, MI>(A, B));
    if constexpr (MI + 1 <= 2 * L) cg_rows<L1, L2, L, MI + 1>(A, B, f);
}

// ============================================================
// Output layout (float4 units). Parts l=0..4 concatenated:
// shapes (1024, 2l+1, n_l*512, 2), n = {3, 6, 6, 3, 1}.
// ============================================================
static constexpr int P1 = 786432;
static constexpr int P2 = 5505024;
static constexpr int P3 = 13369344;
static constexpr int P4 = 18874368;

// Single pass (no duplicated input traffic), float4 = 2 complex channels
// per thread -> 512B per warp-store (half the write streams of float2),
// recompute products on the fly, 2 CTAs/SM via launch_bounds cap.
__global__ void __launch_bounds__(256, 2) cg_kernel(
    const float4* __restrict__ x0, const float4* __restrict__ x1,
    const float4* __restrict__ x2, float4* __restrict__ out) {
    const int c4 = threadIdx.x;  // channel-pair index 0..255
    const int b  = blockIdx.x;   // batch 0..1023

    float4 a0[1], a1[3], a2[5];
    a0[0] = x0[b * 256 + c4];
#pragma unroll
    for (int i = 0; i < 3; ++i) a1[i] = x1[(b * 3 + i) * 256 + c4];
#pragma unroll
    for (int i = 0; i < 5; ++i) a2[i] = x2[(b * 5 + i) * 256 + c4];

    const float4 zf = make_float4(0.f, 0.f, 0.f, 0.f);

    // ---- l=0 part: k0=(0,0,0), k1=(1,1,0), k2=(2,2,0)
    __stcs(&out[b * 768 + c4],           cmul(a0[0], a0[0]));
    __stcs(&out[b * 768 + 256 + c4],     cg_row<1, 1, 0, 0>(a1, a1));
    __stcs(&out[b * 768 + 2 * 256 + c4], cg_row<2, 2, 0, 0>(a2, a2));

    // ---- l=1 part (6 k): k0=(0,1), k1=(1,0) identical (C=1);
    //      k2=(1,1,1)=0, k5=(2,2,1)=0 (antisymmetric self-products).
#pragma unroll
    for (int m = 0; m < 3; ++m) {
        const float4 p = cmul(a0[0], a1[m]);
        const int base = P1 + (b * 3 + m) * 1536 + c4;
        __stcs(&out[base],           p);
        __stcs(&out[base + 256],     p);
        __stcs(&out[base + 2 * 256], zf);
        __stcs(&out[base + 5 * 256], zf);
    }
    // k3=(1,2,1), k4=(2,1,1) (sign +1)
    cg_rows<1, 2, 1>(a1, a2, [&](int mi, float4 v) {
        const int base = P1 + (b * 3 + mi) * 1536 + c4;
        __stcs(&out[base + 3 * 256], v);
        __stcs(&out[base + 4 * 256], v);
    });

    // ---- l=2 part (6 k): k0=(0,2), k3=(2,0) identical (C=1)
#pragma unroll
    for (int m = 0; m < 5; ++m) {
        const float4 p = cmul(a0[0], a2[m]);
        const int base = P2 + (b * 5 + m) * 1536 + c4;
        __stcs(&out[base],           p);
        __stcs(&out[base + 3 * 256], p);
    }
    // k1=(1,1,2)
    cg_rows<1, 1, 2>(a1, a1, [&](int mi, float4 v) {
        __stcs(&out[P2 + (b * 5 + mi) * 1536 + 256 + c4], v);
    });
    // k2=(1,2,2), k4=(2,1,2) = -(1,2,2)
    cg_rows<1, 2, 2>(a1, a2, [&](int mi, float4 v) {
        const int base = P2 + (b * 5 + mi) * 1536 + c4;
        __stcs(&out[base + 2 * 256], v);
        __stcs(&out[base + 4 * 256], neg4(v));
    });
    // k5=(2,2,2)
    cg_rows<2, 2, 2>(a2, a2, [&](int mi, float4 v) {
        __stcs(&out[P2 + (b * 5 + mi) * 1536 + 5 * 256 + c4], v);
    });

    // ---- l=3 part (3 k): k0=(1,2,3), k1=(2,1,3) (+1), k2=(2,2,3)=0
    cg_rows<1, 2, 3>(a1, a2, [&](int mi, float4 v) {
        const int base = P3 + (b * 7 + mi) * 768 + c4;
        __stcs(&out[base],           v);
        __stcs(&out[base + 256],     v);
        __stcs(&out[base + 2 * 256], zf);
    });

    // ---- l=4 part (1 k): (2,2,4)
    cg_rows<2, 2, 4>(a2, a2, [&](int mi, float4 v) {
        __stcs(&out[P4 + (b * 9 + mi) * 256 + c4], v);
    });
}

extern "C" void kernel_launch(void* const* d_in, const int* in_sizes, int n_in,
                              void* d_out, int out_size) {
    const float4* x0 = nullptr;
    const float4* x1 = nullptr;
    const float4* x2 = nullptr;
    for (int i = 0; i < n_in; ++i) {
        if (in_sizes[i] == 1024 * 1 * 512 * 2)      x0 = (const float4*)d_in[i];
        else if (in_sizes[i] == 1024 * 3 * 512 * 2) x1 = (const float4*)d_in[i];
        else if (in_sizes[i] == 1024 * 5 * 512 * 2) x2 = (const float4*)d_in[i];
    }
    cg_kernel<<<1024, 256>>>(x0, x1, x2, (float4*)d_out);
}